// round 1
// baseline (speedup 1.0000x reference)
#include <cuda_runtime.h>
#include <math.h>

// ContactMapHead:
//   h = relu(hs @ W^T + b)          hs:[4,2048,1024] W:[256,1024] -> h:[4,2048,256]
//   scores = (h @ h^T) * clf_w + clf_b   -> [4,2048,2048]
//
// Two fp32 SIMT GEMMs, 64x64 tiles, 4x4 register blocking, 256 threads/block.
// Scores GEMM exploits symmetry: only upper-triangular 64x64 blocks computed,
// off-diagonal blocks mirrored on write.

#define B_  4
#define S_  2048
#define D_  1024
#define P_  256

// Scratch for h (allocation-free rule: __device__ global array)
__device__ float g_h[(size_t)B_ * S_ * P_];   // 32 MB

// ---------------------------------------------------------------------------
// Kernel 1: h = relu(hs @ W^T + b).  M=B*S=8192, N=P=256, K=D=1024.
// Both operands are K-major (row-major with K contiguous) -> NT GEMM.
// ---------------------------------------------------------------------------
__global__ __launch_bounds__(256) void proj_kernel(
    const float* __restrict__ hs,     // [8192,1024]
    const float* __restrict__ W,      // [256,1024]
    const float* __restrict__ bias,   // [256]
    float* __restrict__ hout)         // [8192,256]
{
    __shared__ float As[8][64];   // [k][row]  (transposed for conflict-free reads)
    __shared__ float Bs[8][64];

    const int tid  = threadIdx.x;
    const int tx   = tid & 15;         // 0..15 -> output col group
    const int ty   = tid >> 4;         // 0..15 -> output row group
    const int row0 = blockIdx.y * 64;
    const int col0 = blockIdx.x * 64;

    const int lrow = tid >> 2;         // 0..63
    const int lk   = (tid & 3) * 2;    // 0,2,4,6

    const float* aptr = hs + (size_t)(row0 + lrow) * D_ + lk;
    const float* bptr = W  + (size_t)(col0 + lrow) * D_ + lk;

    float acc[4][4] = {};

    for (int k0 = 0; k0 < D_; k0 += 8) {
        float2 av = *(const float2*)(aptr + k0);
        float2 bv = *(const float2*)(bptr + k0);
        __syncthreads();                    // previous tile fully consumed
        As[lk][lrow]     = av.x;
        As[lk + 1][lrow] = av.y;
        Bs[lk][lrow]     = bv.x;
        Bs[lk + 1][lrow] = bv.y;
        __syncthreads();
#pragma unroll
        for (int k = 0; k < 8; k++) {
            float4 a4 = *(const float4*)&As[k][ty * 4];
            float4 b4 = *(const float4*)&Bs[k][tx * 4];
            float ar[4] = {a4.x, a4.y, a4.z, a4.w};
            float br[4] = {b4.x, b4.y, b4.z, b4.w};
#pragma unroll
            for (int i = 0; i < 4; i++)
#pragma unroll
                for (int j = 0; j < 4; j++)
                    acc[i][j] = fmaf(ar[i], br[j], acc[i][j]);
        }
    }

    float4 bv4 = *(const float4*)&bias[col0 + tx * 4];
    float bb[4] = {bv4.x, bv4.y, bv4.z, bv4.w};
#pragma unroll
    for (int i = 0; i < 4; i++) {
        const int r = row0 + ty * 4 + i;
        float4 o;
        o.x = fmaxf(acc[i][0] + bb[0], 0.f);
        o.y = fmaxf(acc[i][1] + bb[1], 0.f);
        o.z = fmaxf(acc[i][2] + bb[2], 0.f);
        o.w = fmaxf(acc[i][3] + bb[3], 0.f);
        *(float4*)&hout[(size_t)r * P_ + col0 + tx * 4] = o;
    }
}

// ---------------------------------------------------------------------------
// Kernel 2: scores[b] = (h[b] @ h[b]^T) * s + c.   M=N=2048, K=256 per batch.
// Symmetric: grid.x enumerates the 528 upper-tri 64x64 block pairs.
// ---------------------------------------------------------------------------
__global__ __launch_bounds__(256) void scores_kernel(
    const float* __restrict__ h,       // [B,2048,256]
    const float* __restrict__ clf_w,   // [1]
    const float* __restrict__ clf_b,   // [1]
    float* __restrict__ out)           // [B,2048,2048]
{
    __shared__ float As[8][64];
    __shared__ float Bs[8][64];

    // Decode (bi, bj) with bj <= bi from triangular index
    const int idx = blockIdx.x;
    int bi = (int)((sqrtf(8.f * (float)idx + 1.f) - 1.f) * 0.5f);
    while ((bi + 1) * (bi + 2) / 2 <= idx) bi++;
    while (bi * (bi + 1) / 2 > idx)       bi--;
    const int bj = idx - bi * (bi + 1) / 2;

    const int rows0 = bi * 64;
    const int cols0 = bj * 64;

    const float* hb   = h   + (size_t)blockIdx.z * S_ * P_;
    float*       outb = out + (size_t)blockIdx.z * S_ * S_;

    const int tid  = threadIdx.x;
    const int tx   = tid & 15;
    const int ty   = tid >> 4;
    const int lrow = tid >> 2;
    const int lk   = (tid & 3) * 2;

    const float* aptr = hb + (size_t)(rows0 + lrow) * P_ + lk;
    const float* bptr = hb + (size_t)(cols0 + lrow) * P_ + lk;

    float acc[4][4] = {};

    for (int k0 = 0; k0 < P_; k0 += 8) {
        float2 av = *(const float2*)(aptr + k0);
        float2 bv = *(const float2*)(bptr + k0);
        __syncthreads();
        As[lk][lrow]     = av.x;
        As[lk + 1][lrow] = av.y;
        Bs[lk][lrow]     = bv.x;
        Bs[lk + 1][lrow] = bv.y;
        __syncthreads();
#pragma unroll
        for (int k = 0; k < 8; k++) {
            float4 a4 = *(const float4*)&As[k][ty * 4];
            float4 b4 = *(const float4*)&Bs[k][tx * 4];
            float ar[4] = {a4.x, a4.y, a4.z, a4.w};
            float br[4] = {b4.x, b4.y, b4.z, b4.w};
#pragma unroll
            for (int i = 0; i < 4; i++)
#pragma unroll
                for (int j = 0; j < 4; j++)
                    acc[i][j] = fmaf(ar[i], br[j], acc[i][j]);
        }
    }

    const float s = clf_w[0];
    const float c = clf_b[0];

    // Direct block: out[rows0+r][cols0+c]
#pragma unroll
    for (int i = 0; i < 4; i++) {
        const int r = rows0 + ty * 4 + i;
        float4 o;
        o.x = fmaf(acc[i][0], s, c);
        o.y = fmaf(acc[i][1], s, c);
        o.z = fmaf(acc[i][2], s, c);
        o.w = fmaf(acc[i][3], s, c);
        *(float4*)&outb[(size_t)r * S_ + cols0 + tx * 4] = o;
    }

    // Mirrored block: out[cols0+c][rows0+r]  (skip on diagonal)
    if (bi != bj) {
#pragma unroll
        for (int j = 0; j < 4; j++) {
            const int cc = cols0 + tx * 4 + j;
            float4 o;
            o.x = fmaf(acc[0][j], s, c);
            o.y = fmaf(acc[1][j], s, c);
            o.z = fmaf(acc[2][j], s, c);
            o.w = fmaf(acc[3][j], s, c);
            *(float4*)&outb[(size_t)cc * S_ + rows0 + ty * 4] = o;
        }
    }
}

// ---------------------------------------------------------------------------
extern "C" void kernel_launch(void* const* d_in, const int* in_sizes, int n_in,
                              void* d_out, int out_size)
{
    const float* hs     = (const float*)d_in[0];  // [4,2048,1024]
    const float* proj_w = (const float*)d_in[1];  // [256,1024]
    const float* proj_b = (const float*)d_in[2];  // [256]
    const float* clf_w  = (const float*)d_in[3];  // [1,1]
    const float* clf_b  = (const float*)d_in[4];  // [1]
    float* out = (float*)d_out;                   // [4,2048,2048]

    float* h_scratch;
    cudaGetSymbolAddress((void**)&h_scratch, g_h);

    // Kernel 1: projection + relu
    {
        dim3 grid(P_ / 64, (B_ * S_) / 64);   // (4, 128)
        proj_kernel<<<grid, 256>>>(hs, proj_w, proj_b, h_scratch);
    }
    // Kernel 2: symmetric batched h @ h^T
    {
        const int ntiles = S_ / 64;                       // 32
        dim3 grid(ntiles * (ntiles + 1) / 2, 1, B_);      // (528, 1, 4)
        scores_kernel<<<grid, 256>>>(h_scratch, clf_w, clf_b, out);
    }
}

// round 3
// speedup vs baseline: 2.0768x; 2.0768x over previous
#include <cuda_runtime.h>
#include <cuda_bf16.h>
#include <math.h>
#include <cstdint>

// ContactMapHead via HMMA (mma.sync bf16) split-GEMMs. tcgen05 is unavailable:
// the harness PTX target is sm_103 (no 'a'), which rejects tcgen05.*.
//   h      = relu(hs @ W^T + b)        hs:[8192,1024] W:[256,1024]
//   scores = (h @ h^T) * s + c         per batch of 4, S=2048
// fp32 -> (hi,lo) bf16; C = A_hi*B_hi + A_hi*B_lo + A_lo*B_hi (fp32 accum).

#define B_    4
#define S_    2048
#define D_    1024
#define P_    256
#define MROWS 8192

#define BK      32          // K elems per chunk (bf16)
#define STAGES  4
#define ROWB    80          // padded smem row bytes (64 data + 16 pad)
#define STAGEB  (128 * ROWB * 2)        // A + B per stage = 20480
#define SMEM_BYTES (STAGES * STAGEB)    // 81920 (also covers 128x132 f32 epi)

// ---------------- scratch ----------------
__device__ unsigned short g_hs_hi[(size_t)MROWS * D_];
__device__ unsigned short g_hs_lo[(size_t)MROWS * D_];
__device__ unsigned short g_w_hi[(size_t)P_ * D_];
__device__ unsigned short g_w_lo[(size_t)P_ * D_];
__device__ unsigned short g_h_hi[(size_t)MROWS * P_];
__device__ unsigned short g_h_lo[(size_t)MROWS * P_];

// ---------------- asm helpers ----------------
__device__ __forceinline__ uint32_t smem_u32(const void* p) {
    uint32_t a;
    asm("{ .reg .u64 t; cvta.to.shared.u64 t, %1; cvt.u32.u64 %0, t; }" : "=r"(a) : "l"(p));
    return a;
}
__device__ __forceinline__ void cpa16(uint32_t s, const void* g) {
    asm volatile("cp.async.cg.shared.global [%0], [%1], 16;" :: "r"(s), "l"(g));
}
#define CP_COMMIT() asm volatile("cp.async.commit_group;" ::: "memory")
#define CP_WAIT2()  asm volatile("cp.async.wait_group 2;" ::: "memory")

#define LDMX4(r, addr) \
    asm volatile("ldmatrix.sync.aligned.m8n8.x4.shared.b16 {%0,%1,%2,%3}, [%4];" \
        : "=r"((r)[0]), "=r"((r)[1]), "=r"((r)[2]), "=r"((r)[3]) : "r"(addr))

#define MMA16816(d, a, b0, b1) \
    asm volatile("mma.sync.aligned.m16n8k16.row.col.f32.bf16.bf16.f32 " \
        "{%0,%1,%2,%3},{%4,%5,%6,%7},{%8,%9},{%0,%1,%2,%3};" \
        : "+f"((d)[0]), "+f"((d)[1]), "+f"((d)[2]), "+f"((d)[3]) \
        : "r"((a)[0]), "r"((a)[1]), "r"((a)[2]), "r"((a)[3]), "r"(b0), "r"(b1))

// ---------------- fp32 -> (hi,lo) bf16 ----------------
__global__ __launch_bounds__(256) void convert_kernel(
    const float* __restrict__ src, unsigned short* __restrict__ hi,
    unsigned short* __restrict__ lo, int n4)
{
    int i = blockIdx.x * 256 + threadIdx.x;
    if (i >= n4) return;
    float4 v = ((const float4*)src)[i];
    ushort4 h, l;
    float f; __nv_bfloat16 b;
    b = __float2bfloat16(v.x); h.x = *(unsigned short*)&b; f = v.x - __bfloat162float(b);
    b = __float2bfloat16(f);   l.x = *(unsigned short*)&b;
    b = __float2bfloat16(v.y); h.y = *(unsigned short*)&b; f = v.y - __bfloat162float(b);
    b = __float2bfloat16(f);   l.y = *(unsigned short*)&b;
    b = __float2bfloat16(v.z); h.z = *(unsigned short*)&b; f = v.z - __bfloat162float(b);
    b = __float2bfloat16(f);   l.z = *(unsigned short*)&b;
    b = __float2bfloat16(v.w); h.w = *(unsigned short*)&b; f = v.w - __bfloat162float(b);
    b = __float2bfloat16(f);   l.w = *(unsigned short*)&b;
    ((ushort4*)hi)[i] = h;
    ((ushort4*)lo)[i] = l;
}

// ---------------- GEMM machinery ----------------
struct GemmSrc {
    const unsigned short *ahi, *alo, *bhi, *blo;
    int K, cpp;   // native K, chunks per phase = K/BK
};

__device__ __forceinline__ void load_chunk(
    uint32_t sbase, int slot, const GemmSrc& g, int c,
    int arow0, int brow0, int tid)
{
    int p    = c / g.cpp;
    int koff = (c - p * g.cpp) * BK;
    const unsigned short* A = (p < 2)  ? g.ahi : g.alo;
    const unsigned short* B = (p == 1) ? g.blo : g.bhi;
    uint32_t sA = sbase + slot * STAGEB;
    uint32_t sB = sA + 128 * ROWB;
#pragma unroll
    for (int i = 0; i < 2; i++) {
        int ch = tid + i * 256;
        int row = ch >> 2, c16 = ch & 3;
        cpa16(sA + row * ROWB + c16 * 16, A + (size_t)(arow0 + row) * g.K + koff + c16 * 8);
    }
#pragma unroll
    for (int i = 0; i < 2; i++) {
        int ch = tid + i * 256;
        int row = ch >> 2, c16 = ch & 3;
        cpa16(sB + row * ROWB + c16 * 16, B + (size_t)(brow0 + row) * g.K + koff + c16 * 8);
    }
}

// 128x128 CTA tile, 8 warps (2x4), warp tile 64x32, acc[4][4][4] fp32.
__device__ __forceinline__ void gemm_main(
    uint32_t sbase, const GemmSrc& g, int NC, int arow0, int brow0,
    float acc[4][4][4])
{
    const int tid = threadIdx.x, lane = tid & 31, w = tid >> 5;
    const int wm = w & 1, wn = w >> 1;

#pragma unroll
    for (int i = 0; i < STAGES - 1; i++) {
        load_chunk(sbase, i, g, i, arow0, brow0, tid);
        CP_COMMIT();
    }

    const uint32_t arowoff = (wm * 64 + (lane & 15)) * ROWB + (lane >> 4) * 16;
    const uint32_t browoff = (wn * 32 + (lane & 15)) * ROWB + (lane >> 4) * 16;

    for (int c = 0; c < NC; c++) {
        CP_WAIT2();
        __syncthreads();
        if (c + STAGES - 1 < NC)
            load_chunk(sbase, (c + STAGES - 1) & (STAGES - 1), g, c + STAGES - 1,
                       arow0, brow0, tid);
        CP_COMMIT();

        uint32_t sA = sbase + (c & (STAGES - 1)) * STAGEB;
        uint32_t sB = sA + 128 * ROWB;
#pragma unroll
        for (int k16 = 0; k16 < 2; k16++) {
            uint32_t a[4][4], b[2][4];
#pragma unroll
            for (int mt = 0; mt < 4; mt++)
                LDMX4(a[mt], sA + arowoff + mt * 16 * ROWB + k16 * 32);
#pragma unroll
            for (int np = 0; np < 2; np++)
                LDMX4(b[np], sB + browoff + np * 16 * ROWB + k16 * 32);
#pragma unroll
            for (int mt = 0; mt < 4; mt++)
#pragma unroll
                for (int nt = 0; nt < 4; nt++)
                    MMA16816(acc[mt][nt], a[mt], b[nt >> 1][nt & 1], b[nt >> 1][(nt & 1) + 2]);
        }
    }
    __syncthreads();   // stage smem may be reused by epilogue
}

// ---------------- proj: h = relu(hs@W^T + b) -> hi/lo bf16 ----------------
__global__ __launch_bounds__(256) void proj_gemm_kernel(const float* __restrict__ bias)
{
    extern __shared__ char smem[];
    uint32_t sbase = smem_u32(smem);
    float acc[4][4][4] = {};

    GemmSrc g;
    g.ahi = g_hs_hi; g.alo = g_hs_lo; g.bhi = g_w_hi; g.blo = g_w_lo;
    g.K = D_; g.cpp = D_ / BK;

    const int row0 = blockIdx.y * 128, col0 = blockIdx.x * 128;
    gemm_main(sbase, g, 3 * (D_ / BK), row0, col0, acc);

    const int lane = threadIdx.x & 31, w = threadIdx.x >> 5;
    const int wm = w & 1, wn = w >> 1;
    uint32_t* hhi = (uint32_t*)g_h_hi;
    uint32_t* hlo = (uint32_t*)g_h_lo;

#pragma unroll
    for (int nt = 0; nt < 4; nt++) {
        int col = col0 + wn * 32 + nt * 8 + (lane & 3) * 2;
        float b0 = bias[col], b1 = bias[col + 1];
#pragma unroll
        for (int mt = 0; mt < 4; mt++) {
            int r0 = row0 + wm * 64 + mt * 16 + (lane >> 2);
#pragma unroll
            for (int hh = 0; hh < 2; hh++) {
                int r = r0 + hh * 8;
                float v0 = fmaxf(acc[mt][nt][hh * 2 + 0] + b0, 0.f);
                float v1 = fmaxf(acc[mt][nt][hh * 2 + 1] + b1, 0.f);
                __nv_bfloat16 h0 = __float2bfloat16(v0), h1 = __float2bfloat16(v1);
                float l0f = v0 - __bfloat162float(h0);
                float l1f = v1 - __bfloat162float(h1);
                __nv_bfloat16 l0 = __float2bfloat16(l0f), l1 = __float2bfloat16(l1f);
                uint32_t hp = (uint32_t)*(unsigned short*)&h0 | ((uint32_t)*(unsigned short*)&h1 << 16);
                uint32_t lp = (uint32_t)*(unsigned short*)&l0 | ((uint32_t)*(unsigned short*)&l1 << 16);
                size_t o = ((size_t)r * P_ + col) >> 1;
                hhi[o] = hp;
                hlo[o] = lp;
            }
        }
    }
}

// ---------------- scores: out = (h@h^T)*s + c (triangular + mirror) ----------------
__global__ __launch_bounds__(256) void scores_gemm_kernel(
    const float* __restrict__ clf_w, const float* __restrict__ clf_b,
    float* __restrict__ out)
{
    extern __shared__ char smem[];
    uint32_t sbase = smem_u32(smem);

    const int idx = blockIdx.x;
    int bi = (int)((sqrtf(8.f * (float)idx + 1.f) - 1.f) * 0.5f);
    while ((bi + 1) * (bi + 2) / 2 <= idx) bi++;
    while (bi * (bi + 1) / 2 > idx)       bi--;
    const int bj = idx - bi * (bi + 1) / 2;
    const int rows0 = bi * 128, cols0 = bj * 128;

    const size_t hoff = (size_t)blockIdx.z * S_ * P_;
    float* outb = out + (size_t)blockIdx.z * S_ * S_;

    float acc[4][4][4] = {};
    GemmSrc g;
    g.ahi = g_h_hi + hoff; g.alo = g_h_lo + hoff;
    g.bhi = g_h_hi + hoff; g.blo = g_h_lo + hoff;
    g.K = P_; g.cpp = P_ / BK;
    gemm_main(sbase, g, 3 * (P_ / BK), rows0, cols0, acc);

    const float sw = clf_w[0], cb = clf_b[0];
    const int lane = threadIdx.x & 31, w = threadIdx.x >> 5;
    const int wm = w & 1, wn = w >> 1;
    float* sep = (float*)smem;   // [128][132]

#pragma unroll
    for (int mt = 0; mt < 4; mt++)
#pragma unroll
        for (int nt = 0; nt < 4; nt++) {
            int lr = wm * 64 + mt * 16 + (lane >> 2);
            int lc = wn * 32 + nt * 8 + (lane & 3) * 2;
            sep[lr * 132 + lc]           = acc[mt][nt][0];
            sep[lr * 132 + lc + 1]       = acc[mt][nt][1];
            sep[(lr + 8) * 132 + lc]     = acc[mt][nt][2];
            sep[(lr + 8) * 132 + lc + 1] = acc[mt][nt][3];
        }
    __syncthreads();

    // direct block (coalesced rows)
#pragma unroll
    for (int pass = 0; pass < 16; pass++) {
        int r = pass * 8 + w;
        float4 v = *(const float4*)(sep + r * 132 + lane * 4);
        v.x = fmaf(v.x, sw, cb); v.y = fmaf(v.y, sw, cb);
        v.z = fmaf(v.z, sw, cb); v.w = fmaf(v.w, sw, cb);
        *(float4*)&outb[(size_t)(rows0 + r) * S_ + cols0 + lane * 4] = v;
    }
    // mirrored block (coalesced rows of the transposed tile)
    if (bi != bj) {
#pragma unroll
        for (int pass = 0; pass < 16; pass++) {
            int c = pass * 8 + w;
            float4 v;
            v.x = fmaf(sep[(lane * 4 + 0) * 132 + c], sw, cb);
            v.y = fmaf(sep[(lane * 4 + 1) * 132 + c], sw, cb);
            v.z = fmaf(sep[(lane * 4 + 2) * 132 + c], sw, cb);
            v.w = fmaf(sep[(lane * 4 + 3) * 132 + c], sw, cb);
            *(float4*)&outb[(size_t)(cols0 + c) * S_ + rows0 + lane * 4] = v;
        }
    }
}

// ---------------- launch ----------------
extern "C" void kernel_launch(void* const* d_in, const int* in_sizes, int n_in,
                              void* d_out, int out_size)
{
    const float* hs     = (const float*)d_in[0];
    const float* proj_w = (const float*)d_in[1];
    const float* proj_b = (const float*)d_in[2];
    const float* clf_w  = (const float*)d_in[3];
    const float* clf_b  = (const float*)d_in[4];
    float* out = (float*)d_out;

    unsigned short *hs_hi, *hs_lo, *w_hi, *w_lo;
    cudaGetSymbolAddress((void**)&hs_hi, g_hs_hi);
    cudaGetSymbolAddress((void**)&hs_lo, g_hs_lo);
    cudaGetSymbolAddress((void**)&w_hi,  g_w_hi);
    cudaGetSymbolAddress((void**)&w_lo,  g_w_lo);

    cudaFuncSetAttribute(proj_gemm_kernel,
                         cudaFuncAttributeMaxDynamicSharedMemorySize, SMEM_BYTES);
    cudaFuncSetAttribute(scores_gemm_kernel,
                         cudaFuncAttributeMaxDynamicSharedMemorySize, SMEM_BYTES);

    {   // fp32 -> hi/lo bf16
        int n4 = (MROWS * D_) / 4;
        convert_kernel<<<(n4 + 255) / 256, 256>>>(hs, hs_hi, hs_lo, n4);
        int w4 = (P_ * D_) / 4;
        convert_kernel<<<(w4 + 255) / 256, 256>>>(proj_w, w_hi, w_lo, w4);
    }
    {   // projection + relu + resplit
        dim3 grid(P_ / 128, MROWS / 128);   // (2, 64)
        proj_gemm_kernel<<<grid, 256, SMEM_BYTES>>>(proj_b);
    }
    {   // symmetric scores
        const int nt = S_ / 128;                 // 16
        dim3 grid(nt * (nt + 1) / 2, 1, B_);     // (136, 1, 4)
        scores_gemm_kernel<<<grid, 256, SMEM_BYTES>>>(clf_w, clf_b, out);
    }
}